// round 15
// baseline (speedup 1.0000x reference)
#include <cuda_runtime.h>
#include <cuda_fp16.h>
#include <cuda_bf16.h>
#include <cstdint>

// Problem constants
#define BB 64      // batch
#define SS 64      // src length (encoder steps)
#define TD 31      // decoder steps (T-1)
#define EE 256     // embed dim
#define HH 512     // hidden
#define GG 2048    // 4*H gates
#define VV 32000   // vocab
#define NENC (SS*BB)   // 4096 rows
#define NDEC (TD*BB)   // 1984 rows
#define NSTEP (SS+TD)  // 95
#define RGRID 128      // recurrence CTAs (<= SM count -> co-resident)
#define MPAD 2048      // padded hseq rows for fc M tiles

// -------- device scratch (allocation-free rule: __device__ globals) --------
__device__ float g_xp_enc[(size_t)NENC * GG];   // 33.5 MB [t*64+b][g]
__device__ float g_xp_dec[(size_t)NDEC * GG];   // 16.3 MB
__device__ float g_h[2][BB * HH];               // ping-pong hidden state
__device__ __half g_Whf[(size_t)VV * HH];       // 33.5 MB fp16 fc W
__device__ __half g_Ahf[(size_t)MPAD * HH];     // 2 MB fp16 hseq (pad rows stay 0)
__device__ __half g_embE[(size_t)VV * EE];      // 16.4 MB fp16 enc_emb
__device__ __half g_embD[(size_t)VV * EE];      // 16.4 MB fp16 dec_emb
__device__ __half g_wihE[(size_t)GG * EE];      // 1 MB fp16 enc_Wih
__device__ __half g_wihD[(size_t)GG * EE];      // 1 MB fp16 dec_Wih

// grid-barrier state: cumulative counters -> replay-safe without reset
__device__ unsigned g_arrive;
__device__ unsigned g_epoch;

// ---------------------------------------------------------------------------
// init: zero out[:,0,:]
// ---------------------------------------------------------------------------
__global__ void init_kernel(float* __restrict__ out) {
    long idx = ((long)blockIdx.x * 256 + threadIdx.x) * 4;
    if (idx < (long)BB * VV) {
        long b = idx / VV, v = idx - b * VV;
        *(float4*)(out + b * (32L * VV) + v) = make_float4(0.f, 0.f, 0.f, 0.f);
    }
}

// ---------------------------------------------------------------------------
// fp32 -> fp16 conversions
// ---------------------------------------------------------------------------
__device__ __forceinline__ void cv8(const float* s, __half* d, long off) {
    float4 v0 = *(const float4*)(s + off);
    float4 v1 = *(const float4*)(s + off + 4);
    __half h[8];
    h[0] = __float2half_rn(v0.x); h[1] = __float2half_rn(v0.y);
    h[2] = __float2half_rn(v0.z); h[3] = __float2half_rn(v0.w);
    h[4] = __float2half_rn(v1.x); h[5] = __float2half_rn(v1.y);
    h[6] = __float2half_rn(v1.z); h[7] = __float2half_rn(v1.w);
    *(uint4*)(d + off) = *(const uint4*)h;
}

__global__ __launch_bounds__(256) void conv_f16(
    const float* __restrict__ src, long nElem,
    __half* __restrict__ dst, long total)
{
    long i = ((long)blockIdx.x * 256 + threadIdx.x) * 8;
    if (i >= total) return;
    if (i + 8 <= nElem) { cv8(src, dst, i); return; }
    __half h[8];
#pragma unroll
    for (int j = 0; j < 8; ++j)
        h[j] = __float2half_rn((i + j < nElem) ? src[i + j] : 0.f);
    *(uint4*)(dst + i) = *(const uint4*)h;
}

__global__ __launch_bounds__(256) void conv4_f16(
    const float* __restrict__ s0, const float* __restrict__ s1,
    const float* __restrict__ s2, const float* __restrict__ s3,
    __half* __restrict__ d0, __half* __restrict__ d1,
    __half* __restrict__ d2, __half* __restrict__ d3)
{
    const long VE = (long)VV * EE, GE = (long)GG * EE;
    long i = ((long)blockIdx.x * 256 + threadIdx.x) * 8;
    if (i < VE)                { cv8(s0, d0, i); }
    else if (i < 2 * VE)       { cv8(s1, d1, i - VE); }
    else if (i < 2 * VE + GE)  { cv8(s2, d2, i - 2 * VE); }
    else if (i < 2 * VE + 2 * GE) { cv8(s3, d3, i - 2 * VE - GE); }
}

// ---------------------------------------------------------------------------
// Shared mma/ldmatrix helpers (fp16, m16n8k16, f32 accum)
// ---------------------------------------------------------------------------
__device__ __forceinline__ uint32_t smem_u32(const void* p) {
    uint32_t a;
    asm("{ .reg .u64 t; cvta.to.shared.u64 t, %1; cvt.u32.u64 %0, t; }"
        : "=r"(a) : "l"(p));
    return a;
}
__device__ __forceinline__ void cp16b(uint32_t smem_addr, const void* gmem) {
    asm volatile("cp.async.ca.shared.global [%0], [%1], 16;" :: "r"(smem_addr), "l"(gmem));
}
__device__ __forceinline__ void cp16g(uint32_t smem_addr, const void* gmem) {
    asm volatile("cp.async.cg.shared.global [%0], [%1], 16;" :: "r"(smem_addr), "l"(gmem));
}
#define CP_COMMIT() asm volatile("cp.async.commit_group;")
#define CP_WAIT(n)  asm volatile("cp.async.wait_group %0;" :: "n"(n))

#define LDSM4(r, a) \
    asm volatile("ldmatrix.sync.aligned.m8n8.x4.shared.b16 {%0,%1,%2,%3}, [%4];" \
        : "=r"((r)[0]), "=r"((r)[1]), "=r"((r)[2]), "=r"((r)[3]) : "r"(a))

__device__ __forceinline__ void mma_f16(float* d, const uint32_t* a, const uint32_t* b) {
    asm volatile(
        "mma.sync.aligned.m16n8k16.row.col.f32.f16.f16.f32 "
        "{%0,%1,%2,%3}, {%4,%5,%6,%7}, {%8,%9}, {%0,%1,%2,%3};"
        : "+f"(d[0]), "+f"(d[1]), "+f"(d[2]), "+f"(d[3])
        : "r"(a[0]), "r"(a[1]), "r"(a[2]), "r"(a[3]), "r"(b[0]), "r"(b[1]));
}

// swizzled 16B-unit offset for (row, chunk) in a 128x32 fp16 tile (64B rows)
__device__ __forceinline__ uint32_t swz16(int row, int chunk) {
    return (uint32_t)(row * 4 + (chunk ^ ((row >> 1) & 3)));
}

// ---------------------------------------------------------------------------
// fc GEMM: CTA 128x128, 8 warps (4m x 2n), warp tile 32x64.
//   K-chunk 64 (8 chunks), 3-stage cp.async ring, smem-staged epilogue.
//   R15: fragment double-buffering -> back-to-back HMMA issue.
// ---------------------------------------------------------------------------
#define FC_STG 32768             // bytes per stage (A 16KB + B 16KB)
#define EP_STRIDE 136            // fp32 epilogue smem row stride

__global__ __launch_bounds__(256) void fc_f16(
    const __half* __restrict__ A, const __half* __restrict__ W,
    const float* __restrict__ bias, float* __restrict__ out)
{
    extern __shared__ __half fsm[];
    const int tid = threadIdx.x, wid = tid >> 5, lane = tid & 31;
    const int wm = wid & 3, wn = wid >> 2;
    const int mBase = blockIdx.y * 128;
    const long nBase = (long)blockIdx.x * 128;
    const uint32_t sb = smem_u32(fsm);

    const int mat = lane >> 3;           // 0..3
    const int abit = mat >> 1, bbit = mat & 1;
    int rA[2], rB[4];
#pragma unroll
    for (int mi = 0; mi < 2; ++mi) rA[mi] = wm * 32 + mi * 16 + (mat & 1) * 8 + (lane & 7);
#pragma unroll
    for (int nj = 0; nj < 4; ++nj) rB[nj] = wn * 64 + nj * 16 + (mat >> 1) * 8 + (lane & 7);

    float acc[2][8][4] = {};

#define FC_STAGE(s, kc) do {                                                \
        uint32_t base = sb + (s) * FC_STG;                                  \
        for (int it = 0; it < 4; ++it) {                                    \
            int idx = it * 256 + tid;          /* 0..1023 */                \
            int row = idx >> 3, ch = idx & 7;                               \
            uint32_t sw = (uint32_t)(row * 8 + (ch ^ (row & 7))) * 16;      \
            cp16b(base + sw,                                                \
                  A + (long)(mBase + row) * HH + (kc) * 64 + ch * 8);       \
            cp16g(base + 16384 + sw,                                        \
                  W + (nBase + row) * (long)HH + (kc) * 64 + ch * 8);       \
        }                                                                   \
        CP_COMMIT();                                                        \
    } while (0)

#define LOADFRAGS(dst, aT_, bT_, ks_) do {                                   \
        _Pragma("unroll")                                                    \
        for (int mi = 0; mi < 2; ++mi) {                                     \
            uint32_t c = (uint32_t)((2 * (ks_) + abit) ^ (rA[mi] & 7));      \
            LDSM4(af2[dst][mi], (aT_) + (uint32_t)(rA[mi] * 8 + c) * 16);    \
        }                                                                    \
        _Pragma("unroll")                                                    \
        for (int nj = 0; nj < 4; ++nj) {                                     \
            uint32_t c = (uint32_t)((2 * (ks_) + bbit) ^ (rB[nj] & 7));      \
            LDSM4(bf2[dst][nj], (bT_) + (uint32_t)(rB[nj] * 8 + c) * 16);    \
        }                                                                    \
    } while (0)

    FC_STAGE(0, 0);
    FC_STAGE(1, 1);
    int sCur = 0;
    uint32_t af2[2][2][4], bf2[2][4][4];
    for (int kc = 0; kc < 8; ++kc) {
        if (kc < 7) { CP_WAIT(1); } else { CP_WAIT(0); }
        __syncthreads();                  // chunk kc visible; buf (kc+2)%3 free
        if (kc + 2 < 8) FC_STAGE((sCur + 2 >= 3) ? sCur - 1 : sCur + 2, kc + 2);
        const uint32_t aT = sb + sCur * FC_STG;
        const uint32_t bT = aT + 16384;
        LOADFRAGS(0, aT, bT, 0);
#pragma unroll
        for (int ks = 0; ks < 4; ++ks) {
            const int cur = ks & 1;
            if (ks < 3) LOADFRAGS(cur ^ 1, aT, bT, ks + 1);
#pragma unroll
            for (int mi = 0; mi < 2; ++mi)
#pragma unroll
                for (int ni = 0; ni < 8; ++ni)
                    mma_f16(acc[mi][ni], af2[cur][mi], bf2[cur][ni >> 1] + (ni & 1) * 2);
        }
        sCur = (sCur == 2) ? 0 : sCur + 1;
    }
#undef FC_STAGE
#undef LOADFRAGS

    // ---- staged epilogue: acc(+bias) -> smem tile -> coalesced STG.128 ----
    __syncthreads();
    float* sOut = (float*)fsm;             // reuse stage smem: 128 x EP_STRIDE
    {
        const int mRow = wm * 32 + (lane >> 2);
        const int nLoc0 = wn * 64 + (lane & 3) * 2;
#pragma unroll
        for (int ni = 0; ni < 8; ++ni) {
            int nl = nLoc0 + ni * 8;
            float2 bv = *(const float2*)(bias + nBase + nl);
#pragma unroll
            for (int mi = 0; mi < 2; ++mi) {
                int r0 = mRow + mi * 16;
                *(float2*)(sOut + r0 * EP_STRIDE + nl) =
                    make_float2(acc[mi][ni][0] + bv.x, acc[mi][ni][1] + bv.y);
                *(float2*)(sOut + (r0 + 8) * EP_STRIDE + nl) =
                    make_float2(acc[mi][ni][2] + bv.x, acc[mi][ni][3] + bv.y);
            }
        }
    }
    __syncthreads();
#pragma unroll
    for (int i = 0; i < 16; ++i) {
        int r = wid * 16 + i;
        int m = mBase + r;
        if (m < NDEC) {
            int b = m & 63, t = m >> 6;
            float4 v = *(const float4*)(sOut + r * EP_STRIDE + lane * 4);
            *(float4*)(out + (long)(b * 32 + t + 1) * VV + nBase + lane * 4) = v;
        }
    }
}

// ---------------------------------------------------------------------------
// xp GEMM (fp16 tensor): xp[r][n] = emb16[tok[r]] . Wih16[n] + bih[n]+bhh[n]
// ---------------------------------------------------------------------------
__global__ __launch_bounds__(128) void xp_f16(
    const __half* __restrict__ emb, const int* __restrict__ tok,
    int tokStride, int nRows,
    const __half* __restrict__ Wih,
    const float* __restrict__ bias0, const float* __restrict__ bias1,
    float* __restrict__ xp)
{
    __shared__ __half sA[2][128 * 32];
    __shared__ __half sB[2][128 * 32];
    __shared__ int stok[128];
    const int tid = threadIdx.x, wid = tid >> 5, lane = tid & 31;
    const int wm = wid & 1, wn = wid >> 1;
    const int mBase = blockIdx.y * 128;
    const int nBase = blockIdx.x * 128;
    const uint32_t sAb = smem_u32(sA), sBb = smem_u32(sB);

    if (tid < 128) {
        int r = mBase + tid;
        if (r >= nRows) r = nRows - 1;
        stok[tid] = tok[(r & 63) * tokStride + (r >> 6)];
    }
    __syncthreads();

    const int mat = lane >> 3;
    const int rowA = wm * 64 + (mat & 1) * 8 + (lane & 7);
    const int swA = (rowA >> 1) & 3;
    const uint32_t aOff0 = (rowA * 4 + (((mat >> 1) + 0) ^ swA)) * 16;
    const uint32_t aOff1 = (rowA * 4 + (((mat >> 1) + 2) ^ swA)) * 16;
    const int rowB = wn * 64 + (mat >> 1) * 8 + (lane & 7);
    const int swB = (rowB >> 1) & 3;
    const uint32_t bOff0 = (rowB * 4 + (((mat & 1) + 0) ^ swB)) * 16;
    const uint32_t bOff1 = (rowB * 4 + (((mat & 1) + 2) ^ swB)) * 16;

    float acc[4][8][4] = {};

#define XP_STAGE(buf, kc) do {                                              \
        for (int it = 0; it < 4; ++it) {                                    \
            int idx = it * 128 + tid;                                       \
            int row = idx >> 2, ch = idx & 3;                               \
            cp16b(sAb + (buf) * 8192 + swz16(row, ch) * 16,                 \
                  emb + (long)stok[row] * EE + (kc) * 32 + ch * 8);         \
            cp16b(sBb + (buf) * 8192 + swz16(row, ch) * 16,                 \
                  Wih + (long)(nBase + row) * EE + (kc) * 32 + ch * 8);     \
        }                                                                   \
        CP_COMMIT();                                                        \
    } while (0)

    XP_STAGE(0, 0);
    for (int kc = 0; kc < 8; ++kc) {
        const int buf = kc & 1;
        __syncthreads();
        if (kc + 1 < 8) XP_STAGE(buf ^ 1, kc + 1);
        if (kc + 1 < 8) { CP_WAIT(1); } else { CP_WAIT(0); }
        __syncthreads();

        const uint32_t aT = sAb + buf * 8192;
        const uint32_t bT = sBb + buf * 8192;
#pragma unroll
        for (int ks = 0; ks < 2; ++ks) {
            const uint32_t ao = ks ? aOff1 : aOff0;
            const uint32_t bo = ks ? bOff1 : bOff0;
            uint32_t af[4][4], bf[4][4];
#pragma unroll
            for (int mi = 0; mi < 4; ++mi)
                LDSM4(af[mi], aT + ao + mi * 1024);
#pragma unroll
            for (int nj = 0; nj < 4; ++nj)
                LDSM4(bf[nj], bT + bo + nj * 1024);
#pragma unroll
            for (int mi = 0; mi < 4; ++mi)
#pragma unroll
                for (int ni = 0; ni < 8; ++ni)
                    mma_f16(acc[mi][ni], af[mi], bf[ni >> 1] + (ni & 1) * 2);
        }
    }
#undef XP_STAGE

    const int mTop = mBase + wm * 64 + (lane >> 2);
    const int nCol = nBase + wn * 64 + (lane & 3) * 2;
#pragma unroll
    for (int ni = 0; ni < 8; ++ni) {
        int n = nCol + ni * 8;
        float2 bv = make_float2(bias0[n] + bias1[n], bias0[n + 1] + bias1[n + 1]);
#pragma unroll
        for (int mi = 0; mi < 4; ++mi) {
            int m0 = mTop + mi * 16;
            if (m0 < nRows) {
                float2 v = make_float2(acc[mi][ni][0] + bv.x, acc[mi][ni][1] + bv.y);
                *(float2*)(xp + (long)m0 * GG + n) = v;
            }
            int m1 = m0 + 8;
            if (m1 < nRows) {
                float2 v = make_float2(acc[mi][ni][2] + bv.x, acc[mi][ni][3] + bv.y);
                *(float2*)(xp + (long)m1 * GG + n) = v;
            }
        }
    }
}

// ---------------------------------------------------------------------------
// Persistent fused LSTM recurrence.
//   R15: 4-chunk h staging (finer cp.async overlap); decoder h stored
//   directly as fp16 into g_Ahf (convA fused away; pad rows stay zero).
// ---------------------------------------------------------------------------
__device__ __forceinline__ float sigf(float x) { return 1.f / (1.f + __expf(-x)); }

__device__ __forceinline__ void grid_sync() {
    __syncthreads();
    if (threadIdx.x == 0) {
        unsigned t;
        asm volatile("atom.add.acq_rel.gpu.u32 %0, [%1], 1;"
                     : "=r"(t) : "l"(&g_arrive) : "memory");
        unsigned target = t / (unsigned)RGRID + 1u;
        if ((t % (unsigned)RGRID) == (unsigned)(RGRID - 1)) {
            asm volatile("st.release.gpu.u32 [%0], %1;"
                         :: "l"(&g_epoch), "r"(target) : "memory");
        } else {
            unsigned e;
            do {
                asm volatile("ld.acquire.gpu.u32 %0, [%1];"
                             : "=r"(e) : "l"(&g_epoch) : "memory");
            } while (e < target);
        }
    }
    __syncthreads();
}

__device__ __forceinline__ void cp16(float* smem, const float* gmem) {
    unsigned s = (unsigned)__cvta_generic_to_shared(smem);
    asm volatile("cp.async.ca.shared.global [%0], [%1], 16;" :: "r"(s), "l"(gmem));
}

#define FMA2(acc, a, b) \
    asm("fma.rn.f32x2 %0, %1, %2, %0;" : "+l"(acc) : "l"(a), "l"(b))

__device__ __forceinline__ float2 unpack2(unsigned long long v) {
    float2 f;
    asm("mov.b64 {%0, %1}, %2;" : "=f"(f.x), "=f"(f.y) : "l"(v));
    return f;
}
__device__ __forceinline__ float red4(unsigned long long a, unsigned long long b) {
    float2 p = unpack2(a), q = unpack2(b);
    return (p.x + q.x) + (p.y + q.y);
}

#define WS_STRIDE 516
#define WS_FLOATS (16 * WS_STRIDE)
#define HS_FLOATS (64 * WS_STRIDE)

// one compute quarter: k in [k0, k0+128)
#define REC_QUARTER(k0)                                                     \
    _Pragma("unroll 2")                                                     \
    for (int k = (k0); k < (k0) + 128; k += 4) {                            \
        ulonglong2 h1 = *(const ulonglong2*)(hr1 + k);                      \
        ulonglong2 h2 = *(const ulonglong2*)(hr2 + k);                      \
        ulonglong2 w0 = *(const ulonglong2*)(wp0 + k);                      \
        ulonglong2 w1 = *(const ulonglong2*)(wp1 + k);                      \
        ulonglong2 w2 = *(const ulonglong2*)(wp2 + k);                      \
        ulonglong2 w3 = *(const ulonglong2*)(wp3 + k);                      \
        FMA2(B10a, h1.x, w0.x); FMA2(B10b, h1.y, w0.y);                     \
        FMA2(B11a, h1.x, w1.x); FMA2(B11b, h1.y, w1.y);                     \
        FMA2(B12a, h1.x, w2.x); FMA2(B12b, h1.y, w2.y);                     \
        FMA2(B13a, h1.x, w3.x); FMA2(B13b, h1.y, w3.y);                     \
        FMA2(B20a, h2.x, w0.x); FMA2(B20b, h2.y, w0.y);                     \
        FMA2(B21a, h2.x, w1.x); FMA2(B21b, h2.y, w1.y);                     \
        FMA2(B22a, h2.x, w2.x); FMA2(B22b, h2.y, w2.y);                     \
        FMA2(B23a, h2.x, w3.x); FMA2(B23b, h2.y, w3.y);                     \
    }

__global__ __launch_bounds__(128, 1) void lstm_persistent(
    const float* __restrict__ xpE, const float* __restrict__ xpD,
    const float* __restrict__ Wenc, const float* __restrict__ Wdec,
    float* __restrict__ hbuf, __half* __restrict__ ahf)
{
    extern __shared__ float sm[];
    float* w_s = sm;                    // 16 x 516
    float* h_s = sm + WS_FLOATS;        // 64 x 516
    float* c_s = h_s + HS_FLOATS;       // 256

    const int tid = threadIdx.x;        // 0..127
    const int d   = tid & 3;            // hidden unit within CTA
    const int rr  = tid >> 2;           // 0..31; thread owns rows rr, rr+32
    const int J   = blockIdx.x * 4;     // hidden base

    for (int i = tid; i < 16 * 128; i += 128) {
        int c = i >> 7, q = (i & 127) << 2;
        int row = (c >> 2) * 512 + J + (c & 3);
        *(float4*)(w_s + c * WS_STRIDE + q) = *(const float4*)(Wenc + (long)row * HH + q);
    }
    hbuf[(long)rr * HH + J + d] = 0.f;
    hbuf[(long)(rr + 32) * HH + J + d] = 0.f;
    c_s[tid] = 0.f;
    c_s[tid + 128] = 0.f;
    grid_sync();

    const float* hr1 = h_s + rr * WS_STRIDE;
    const float* hr2 = h_s + (rr + 32) * WS_STRIDE;
    const float* wp0 = w_s + (0  + d) * WS_STRIDE;
    const float* wp1 = w_s + (4  + d) * WS_STRIDE;
    const float* wp2 = w_s + (8  + d) * WS_STRIDE;
    const float* wp3 = w_s + (12 + d) * WS_STRIDE;

    const long xb1 = (long)rr * GG + J + d;
    const long xb2 = (long)(rr + 32) * GG + J + d;
    float a10 = xpE[xb1], a11 = xpE[xb1 + 512], a12 = xpE[xb1 + 1024], a13 = xpE[xb1 + 1536];
    float a20 = xpE[xb2], a21 = xpE[xb2 + 512], a22 = xpE[xb2 + 1024], a23 = xpE[xb2 + 1536];

    for (int t = 0; t < NSTEP; ++t) {
        // stage h[t] into SMEM in four 128-col chunks via cp.async
        const float* hin = hbuf + (t & 1) * (BB * HH);
#pragma unroll
        for (int c = 0; c < 4; ++c) {
#pragma unroll
            for (int i = 0; i < 16; ++i) {
                int idx = i * 128 + tid;                 // 0..2047
                int r2 = idx >> 5, q = (idx & 31) << 2;  // 64 rows x 32 float4
                cp16(h_s + r2 * WS_STRIDE + c * 128 + q,
                     hin + r2 * HH + c * 128 + q);
            }
            CP_COMMIT();
        }
        if (t == SS) {   // decoder weight reload (plain loads; no group impact)
            for (int i = tid; i < 16 * 128; i += 128) {
                int c = i >> 7, q = (i & 127) << 2;
                int row = (c >> 2) * 512 + J + (c & 3);
                *(float4*)(w_s + c * WS_STRIDE + q) = *(const float4*)(Wdec + (long)row * HH + q);
            }
        }

        unsigned long long B10a = 0, B10b = 0, B11a = 0, B11b = 0;
        unsigned long long B12a = 0, B12b = 0, B13a = 0, B13b = 0;
        unsigned long long B20a = 0, B20b = 0, B21a = 0, B21b = 0;
        unsigned long long B22a = 0, B22b = 0, B23a = 0, B23b = 0;

        CP_WAIT(3); __syncthreads(); REC_QUARTER(0);
        CP_WAIT(2); __syncthreads(); REC_QUARTER(128);
        CP_WAIT(1); __syncthreads(); REC_QUARTER(256);
        CP_WAIT(0); __syncthreads(); REC_QUARTER(384);

        float gi1 = a10 + red4(B10a, B10b), gf1 = a11 + red4(B11a, B11b);
        float gg1 = a12 + red4(B12a, B12b), go1 = a13 + red4(B13a, B13b);
        float gi2 = a20 + red4(B20a, B20b), gf2 = a21 + red4(B21a, B21b);
        float gg2 = a22 + red4(B22a, B22b), go2 = a23 + red4(B23a, B23b);

        float cn1 = sigf(gf1) * c_s[tid] + sigf(gi1) * tanhf(gg1);
        float hn1 = sigf(go1) * tanhf(cn1);
        c_s[tid] = cn1;
        float cn2 = sigf(gf2) * c_s[tid + 128] + sigf(gi2) * tanhf(gg2);
        float hn2 = sigf(go2) * tanhf(cn2);
        c_s[tid + 128] = cn2;

        float* hout = hbuf + ((t + 1) & 1) * (BB * HH);
        hout[(long)rr * HH + J + d] = hn1;
        hout[(long)(rr + 32) * HH + J + d] = hn2;
        if (t >= SS) {   // fc A operand directly in fp16 (convA fused away)
            __half* hq = ahf + (long)(t - SS) * (BB * HH);
            hq[(long)rr * HH + J + d] = __float2half_rn(hn1);
            hq[(long)(rr + 32) * HH + J + d] = __float2half_rn(hn2);
        }

        if (t + 1 < NSTEP) {
            const float* nxp = (t + 1 < SS) ? (xpE + (long)(t + 1) * (BB * GG))
                                            : (xpD + (long)(t + 1 - SS) * (BB * GG));
            a10 = nxp[xb1]; a11 = nxp[xb1 + 512];
            a12 = nxp[xb1 + 1024]; a13 = nxp[xb1 + 1536];
            a20 = nxp[xb2]; a21 = nxp[xb2 + 512];
            a22 = nxp[xb2 + 1024]; a23 = nxp[xb2 + 1536];
        }

        grid_sync();
    }
}

// ---------------------------------------------------------------------------
// kernel_launch
// ---------------------------------------------------------------------------
extern "C" void kernel_launch(void* const* d_in, const int* in_sizes, int n_in,
                              void* d_out, int out_size) {
    (void)in_sizes; (void)n_in; (void)out_size;
    const int*   src     = (const int*)  d_in[0];
    const int*   tgt     = (const int*)  d_in[1];
    const float* enc_emb = (const float*)d_in[2];
    const float* dec_emb = (const float*)d_in[3];
    const float* enc_Wih = (const float*)d_in[4];
    const float* enc_Whh = (const float*)d_in[5];
    const float* enc_bih = (const float*)d_in[6];
    const float* enc_bhh = (const float*)d_in[7];
    const float* dec_Wih = (const float*)d_in[8];
    const float* dec_Whh = (const float*)d_in[9];
    const float* dec_bih = (const float*)d_in[10];
    const float* dec_bhh = (const float*)d_in[11];
    const float* fc_W    = (const float*)d_in[12];
    const float* fc_b    = (const float*)d_in[13];
    float* out = (float*)d_out;

    float *xpE, *xpD, *hb;
    __half *whf, *ahf, *embE, *embD, *wihE, *wihD;
    cudaGetSymbolAddress((void**)&xpE, g_xp_enc);
    cudaGetSymbolAddress((void**)&xpD, g_xp_dec);
    cudaGetSymbolAddress((void**)&hb,  g_h);
    cudaGetSymbolAddress((void**)&whf, g_Whf);
    cudaGetSymbolAddress((void**)&ahf, g_Ahf);
    cudaGetSymbolAddress((void**)&embE, g_embE);
    cudaGetSymbolAddress((void**)&embD, g_embD);
    cudaGetSymbolAddress((void**)&wihE, g_wihE);
    cudaGetSymbolAddress((void**)&wihD, g_wihD);

    const int recSmem = (WS_FLOATS + HS_FLOATS + 256) * sizeof(float);  // ~166 KB
    cudaFuncSetAttribute(lstm_persistent,
                         cudaFuncAttributeMaxDynamicSharedMemorySize, recSmem);
    const int fcSmem = 3 * FC_STG;                                      // 96 KB
    cudaFuncSetAttribute(fc_f16,
                         cudaFuncAttributeMaxDynamicSharedMemorySize, fcSmem);

    // #1 merged xp-table conversions (embE, embD, wihE, wihD)
    {
        long total = 2L * VV * EE + 2L * GG * EE;
        conv4_f16<<<(int)((total / 8 + 255) / 256), 256>>>(
            enc_emb, dec_emb, enc_Wih, dec_Wih, embE, embD, wihE, wihD);
    }

    // #2, #3 xp GEMMs on fp16 tensor cores
    xp_f16<<<dim3(GG / 128, NENC / 128), 128>>>(
        embE, src, SS, NENC, wihE, enc_bih, enc_bhh, xpE);
    xp_f16<<<dim3(GG / 128, (NDEC + 127) / 128), 128>>>(
        embD, tgt, 32, NDEC, wihD, dec_bih, dec_bhh, xpD);

    // #4 fused persistent recurrence (writes fp16 A for fc directly)
    lstm_persistent<<<RGRID, 128, recSmem>>>(xpE, xpD, enc_Whh, dec_Whh, hb, ahf);

    // #5 zero out[:,0,:]
    init_kernel<<<(BB * VV / 4 + 255) / 256, 256>>>(out);

    // #6 fc_W -> fp16
    {
        long n = (long)VV * HH;
        conv_f16<<<(int)((n / 8 + 255) / 256), 256>>>(fc_W, n, whf, n);
    }

    // #7 vocab projection on fp16 tensor cores -> out[b][t+1][v]
    fc_f16<<<dim3(VV / 128, MPAD / 128), 256, fcSmem>>>(ahf, whf, fc_b, out);
}

// round 16
// speedup vs baseline: 1.0084x; 1.0084x over previous
#include <cuda_runtime.h>
#include <cuda_fp16.h>
#include <cuda_bf16.h>
#include <cstdint>

// Problem constants
#define BB 64      // batch
#define SS 64      // src length (encoder steps)
#define TD 31      // decoder steps (T-1)
#define EE 256     // embed dim
#define HH 512     // hidden
#define GG 2048    // 4*H gates
#define VV 32000   // vocab
#define NENC (SS*BB)   // 4096 rows
#define NDEC (TD*BB)   // 1984 rows
#define NSTEP (SS+TD)  // 95
#define RGRID 128      // recurrence CTAs (<= SM count -> co-resident)
#define MPAD 2048      // padded hseq rows for fc M tiles

// -------- device scratch (allocation-free rule: __device__ globals) --------
__device__ float g_xp_enc[(size_t)NENC * GG];   // 33.5 MB [t*64+b][g]
__device__ float g_xp_dec[(size_t)NDEC * GG];   // 16.3 MB
__device__ float g_h[2][BB * HH];               // ping-pong hidden state
__device__ __half g_Whf[(size_t)VV * HH];       // 33.5 MB fp16 fc W
__device__ __half g_Ahf[(size_t)MPAD * HH];     // 2 MB fp16 hseq (pad rows stay 0)
__device__ __half g_embE[(size_t)VV * EE];      // 16.4 MB fp16 enc_emb
__device__ __half g_embD[(size_t)VV * EE];      // 16.4 MB fp16 dec_emb
__device__ __half g_wihE[(size_t)GG * EE];      // 1 MB fp16 enc_Wih
__device__ __half g_wihD[(size_t)GG * EE];      // 1 MB fp16 dec_Wih

// grid-barrier state: cumulative counters -> replay-safe without reset
__device__ unsigned g_arrive;
__device__ unsigned g_epoch;

// ---------------------------------------------------------------------------
// init: zero out[:,0,:]
// ---------------------------------------------------------------------------
__global__ void init_kernel(float* __restrict__ out) {
    long idx = ((long)blockIdx.x * 256 + threadIdx.x) * 4;
    if (idx < (long)BB * VV) {
        long b = idx / VV, v = idx - b * VV;
        *(float4*)(out + b * (32L * VV) + v) = make_float4(0.f, 0.f, 0.f, 0.f);
    }
}

// ---------------------------------------------------------------------------
// fp32 -> fp16 conversions
// ---------------------------------------------------------------------------
__device__ __forceinline__ void cv8(const float* s, __half* d, long off) {
    float4 v0 = *(const float4*)(s + off);
    float4 v1 = *(const float4*)(s + off + 4);
    __half h[8];
    h[0] = __float2half_rn(v0.x); h[1] = __float2half_rn(v0.y);
    h[2] = __float2half_rn(v0.z); h[3] = __float2half_rn(v0.w);
    h[4] = __float2half_rn(v1.x); h[5] = __float2half_rn(v1.y);
    h[6] = __float2half_rn(v1.z); h[7] = __float2half_rn(v1.w);
    *(uint4*)(d + off) = *(const uint4*)h;
}

__global__ __launch_bounds__(256) void conv_f16(
    const float* __restrict__ src, long nElem,
    __half* __restrict__ dst, long total)
{
    long i = ((long)blockIdx.x * 256 + threadIdx.x) * 8;
    if (i >= total) return;
    if (i + 8 <= nElem) { cv8(src, dst, i); return; }
    __half h[8];
#pragma unroll
    for (int j = 0; j < 8; ++j)
        h[j] = __float2half_rn((i + j < nElem) ? src[i + j] : 0.f);
    *(uint4*)(dst + i) = *(const uint4*)h;
}

__global__ __launch_bounds__(256) void conv4_f16(
    const float* __restrict__ s0, const float* __restrict__ s1,
    const float* __restrict__ s2, const float* __restrict__ s3,
    __half* __restrict__ d0, __half* __restrict__ d1,
    __half* __restrict__ d2, __half* __restrict__ d3)
{
    const long VE = (long)VV * EE, GE = (long)GG * EE;
    long i = ((long)blockIdx.x * 256 + threadIdx.x) * 8;
    if (i < VE)                { cv8(s0, d0, i); }
    else if (i < 2 * VE)       { cv8(s1, d1, i - VE); }
    else if (i < 2 * VE + GE)  { cv8(s2, d2, i - 2 * VE); }
    else if (i < 2 * VE + 2 * GE) { cv8(s3, d3, i - 2 * VE - GE); }
}

// ---------------------------------------------------------------------------
// Shared mma/ldmatrix helpers (fp16, m16n8k16, f32 accum)
// ---------------------------------------------------------------------------
__device__ __forceinline__ uint32_t smem_u32(const void* p) {
    uint32_t a;
    asm("{ .reg .u64 t; cvta.to.shared.u64 t, %1; cvt.u32.u64 %0, t; }"
        : "=r"(a) : "l"(p));
    return a;
}
__device__ __forceinline__ void cp16b(uint32_t smem_addr, const void* gmem) {
    asm volatile("cp.async.ca.shared.global [%0], [%1], 16;" :: "r"(smem_addr), "l"(gmem));
}
#define CP_COMMIT() asm volatile("cp.async.commit_group;")
#define CP_WAIT(n)  asm volatile("cp.async.wait_group %0;" :: "n"(n))

#define LDSM4(r, a) \
    asm volatile("ldmatrix.sync.aligned.m8n8.x4.shared.b16 {%0,%1,%2,%3}, [%4];" \
        : "=r"((r)[0]), "=r"((r)[1]), "=r"((r)[2]), "=r"((r)[3]) : "r"(a))

__device__ __forceinline__ void mma_f16(float* d, const uint32_t* a, const uint32_t* b) {
    asm volatile(
        "mma.sync.aligned.m16n8k16.row.col.f32.f16.f16.f32 "
        "{%0,%1,%2,%3}, {%4,%5,%6,%7}, {%8,%9}, {%0,%1,%2,%3};"
        : "+f"(d[0]), "+f"(d[1]), "+f"(d[2]), "+f"(d[3])
        : "r"(a[0]), "r"(a[1]), "r"(a[2]), "r"(a[3]), "r"(b[0]), "r"(b[1]));
}

// swizzled 16B-unit offset for (row, chunk) in a 128x32 fp16 tile (64B rows)
__device__ __forceinline__ uint32_t swz16(int row, int chunk) {
    return (uint32_t)(row * 4 + (chunk ^ ((row >> 1) & 3)));
}

// ---------------------------------------------------------------------------
// fc GEMM: CTA 128x256, 512 thr = 16 warps (4m x 4n), warp tile 32x64.
//   4 warps/SMSP -> latency hidden. K-chunk 64 (8 chunks), 2-stage ring.
//   Smem-staged 2-phase epilogue, fully coalesced float4 stores.
// ---------------------------------------------------------------------------
#define FC_BN 256
#define FC_STG 49152             // bytes per stage (A 16KB + B 32KB)
#define EP_STRIDE 132            // fp32 epilogue smem row stride

__global__ __launch_bounds__(512) void fc_f16(
    const __half* __restrict__ A, const __half* __restrict__ W,
    const float* __restrict__ bias, float* __restrict__ out)
{
    extern __shared__ __half fsm[];
    const int tid = threadIdx.x, wid = tid >> 5, lane = tid & 31;
    const int wm = wid & 3, wn = wid >> 2;          // 4 x 4 warps
    const int mBase = blockIdx.y * 128;
    const long nBase = (long)blockIdx.x * FC_BN;
    const uint32_t sb = smem_u32(fsm);

    const int mat = lane >> 3;           // 0..3
    const int abit = mat >> 1, bbit = mat & 1;
    int rA[2], rB[4];
#pragma unroll
    for (int mi = 0; mi < 2; ++mi) rA[mi] = wm * 32 + mi * 16 + (mat & 1) * 8 + (lane & 7);
#pragma unroll
    for (int nj = 0; nj < 4; ++nj) rB[nj] = wn * 64 + nj * 16 + (mat >> 1) * 8 + (lane & 7);

    float acc[2][8][4] = {};

    // per stage: A = 128 rows x 8 chunks (1024 units), B = 256 rows x 8 (2048)
#define FC_STAGE(s, kc) do {                                                \
        uint32_t base = sb + (s) * FC_STG;                                  \
        for (int it = 0; it < 6; ++it) {                                    \
            int idx = it * 512 + tid;          /* 0..3071 */                \
            if (idx < 1024) {                                               \
                int row = idx >> 3, ch = idx & 7;                           \
                uint32_t sw = (uint32_t)(row * 8 + (ch ^ (row & 7))) * 16;  \
                cp16b(base + sw,                                            \
                      A + (long)(mBase + row) * HH + (kc) * 64 + ch * 8);   \
            } else {                                                        \
                int rem = idx - 1024;                                       \
                int row = rem >> 3, ch = rem & 7;                           \
                uint32_t sw = (uint32_t)(row * 8 + (ch ^ (row & 7))) * 16;  \
                cp16b(base + 16384 + sw,                                    \
                      W + (nBase + row) * (long)HH + (kc) * 64 + ch * 8);   \
            }                                                               \
        }                                                                   \
        CP_COMMIT();                                                        \
    } while (0)

    FC_STAGE(0, 0);
    for (int kc = 0; kc < 8; ++kc) {
        const int buf = kc & 1;
        __syncthreads();                          // buf^1 consumed by all warps
        if (kc + 1 < 8) FC_STAGE(buf ^ 1, kc + 1);
        if (kc + 1 < 8) { CP_WAIT(1); } else { CP_WAIT(0); }
        __syncthreads();                          // chunk kc visible

        const uint32_t aT = sb + buf * FC_STG;
        const uint32_t bT = aT + 16384;
#pragma unroll
        for (int ks = 0; ks < 4; ++ks) {
            uint32_t af[2][4], bf[4][4];
#pragma unroll
            for (int mi = 0; mi < 2; ++mi) {
                uint32_t c = (uint32_t)((2 * ks + abit) ^ (rA[mi] & 7));
                LDSM4(af[mi], aT + (uint32_t)(rA[mi] * 8 + c) * 16);
            }
#pragma unroll
            for (int nj = 0; nj < 4; ++nj) {
                uint32_t c = (uint32_t)((2 * ks + bbit) ^ (rB[nj] & 7));
                LDSM4(bf[nj], bT + (uint32_t)(rB[nj] * 8 + c) * 16);
            }
#pragma unroll
            for (int mi = 0; mi < 2; ++mi)
#pragma unroll
                for (int ni = 0; ni < 8; ++ni)
                    mma_f16(acc[mi][ni], af[mi], bf[ni >> 1] + (ni & 1) * 2);
        }
    }
#undef FC_STAGE

    // ---- 2-phase staged epilogue: n-halves of the 128x256 tile ----
    float* sOut = (float*)fsm;             // 128 x EP_STRIDE fp32 (67.6 KB)
#pragma unroll 1
    for (int ph = 0; ph < 2; ++ph) {
        __syncthreads();                   // previous contents consumed
        if ((wn >> 1) == ph) {             // warps whose n-range is this half
            const int mRow = wm * 32 + (lane >> 2);
            const int nLoc0 = (wn & 1) * 64 + (lane & 3) * 2;
#pragma unroll
            for (int ni = 0; ni < 8; ++ni) {
                int nl = nLoc0 + ni * 8;
                float2 bv = *(const float2*)(bias + nBase + ph * 128 + nl);
#pragma unroll
                for (int mi = 0; mi < 2; ++mi) {
                    int r0 = mRow + mi * 16;
                    *(float2*)(sOut + r0 * EP_STRIDE + nl) =
                        make_float2(acc[mi][ni][0] + bv.x, acc[mi][ni][1] + bv.y);
                    *(float2*)(sOut + (r0 + 8) * EP_STRIDE + nl) =
                        make_float2(acc[mi][ni][2] + bv.x, acc[mi][ni][3] + bv.y);
                }
            }
        }
        __syncthreads();
        // 16 warps stream 8 rows each: 128 contiguous floats per row
#pragma unroll
        for (int i = 0; i < 8; ++i) {
            int r = wid * 8 + i;
            int m = mBase + r;
            if (m < NDEC) {
                int b = m & 63, t = m >> 6;
                float4 v = *(const float4*)(sOut + r * EP_STRIDE + lane * 4);
                *(float4*)(out + (long)(b * 32 + t + 1) * VV + nBase + ph * 128 + lane * 4) = v;
            }
        }
    }
}

// ---------------------------------------------------------------------------
// xp GEMM (fp16 tensor): xp[r][n] = emb16[tok[r]] . Wih16[n] + bih[n]+bhh[n]
// ---------------------------------------------------------------------------
__global__ __launch_bounds__(128) void xp_f16(
    const __half* __restrict__ emb, const int* __restrict__ tok,
    int tokStride, int nRows,
    const __half* __restrict__ Wih,
    const float* __restrict__ bias0, const float* __restrict__ bias1,
    float* __restrict__ xp)
{
    __shared__ __half sA[2][128 * 32];
    __shared__ __half sB[2][128 * 32];
    __shared__ int stok[128];
    const int tid = threadIdx.x, wid = tid >> 5, lane = tid & 31;
    const int wm = wid & 1, wn = wid >> 1;
    const int mBase = blockIdx.y * 128;
    const int nBase = blockIdx.x * 128;
    const uint32_t sAb = smem_u32(sA), sBb = smem_u32(sB);

    if (tid < 128) {
        int r = mBase + tid;
        if (r >= nRows) r = nRows - 1;
        stok[tid] = tok[(r & 63) * tokStride + (r >> 6)];
    }
    __syncthreads();

    const int mat = lane >> 3;
    const int rowA = wm * 64 + (mat & 1) * 8 + (lane & 7);
    const int swA = (rowA >> 1) & 3;
    const uint32_t aOff0 = (rowA * 4 + (((mat >> 1) + 0) ^ swA)) * 16;
    const uint32_t aOff1 = (rowA * 4 + (((mat >> 1) + 2) ^ swA)) * 16;
    const int rowB = wn * 64 + (mat >> 1) * 8 + (lane & 7);
    const int swB = (rowB >> 1) & 3;
    const uint32_t bOff0 = (rowB * 4 + (((mat & 1) + 0) ^ swB)) * 16;
    const uint32_t bOff1 = (rowB * 4 + (((mat & 1) + 2) ^ swB)) * 16;

    float acc[4][8][4] = {};

#define XP_STAGE(buf, kc) do {                                              \
        for (int it = 0; it < 4; ++it) {                                    \
            int idx = it * 128 + tid;                                       \
            int row = idx >> 2, ch = idx & 3;                               \
            cp16b(sAb + (buf) * 8192 + swz16(row, ch) * 16,                 \
                  emb + (long)stok[row] * EE + (kc) * 32 + ch * 8);         \
            cp16b(sBb + (buf) * 8192 + swz16(row, ch) * 16,                 \
                  Wih + (long)(nBase + row) * EE + (kc) * 32 + ch * 8);     \
        }                                                                   \
        CP_COMMIT();                                                        \
    } while (0)

    XP_STAGE(0, 0);
    for (int kc = 0; kc < 8; ++kc) {
        const int buf = kc & 1;
        __syncthreads();
        if (kc + 1 < 8) XP_STAGE(buf ^ 1, kc + 1);
        if (kc + 1 < 8) { CP_WAIT(1); } else { CP_WAIT(0); }
        __syncthreads();

        const uint32_t aT = sAb + buf * 8192;
        const uint32_t bT = sBb + buf * 8192;
#pragma unroll
        for (int ks = 0; ks < 2; ++ks) {
            const uint32_t ao = ks ? aOff1 : aOff0;
            const uint32_t bo = ks ? bOff1 : bOff0;
            uint32_t af[4][4], bf[4][4];
#pragma unroll
            for (int mi = 0; mi < 4; ++mi)
                LDSM4(af[mi], aT + ao + mi * 1024);
#pragma unroll
            for (int nj = 0; nj < 4; ++nj)
                LDSM4(bf[nj], bT + bo + nj * 1024);
#pragma unroll
            for (int mi = 0; mi < 4; ++mi)
#pragma unroll
                for (int ni = 0; ni < 8; ++ni)
                    mma_f16(acc[mi][ni], af[mi], bf[ni >> 1] + (ni & 1) * 2);
        }
    }
#undef XP_STAGE

    const int mTop = mBase + wm * 64 + (lane >> 2);
    const int nCol = nBase + wn * 64 + (lane & 3) * 2;
#pragma unroll
    for (int ni = 0; ni < 8; ++ni) {
        int n = nCol + ni * 8;
        float2 bv = make_float2(bias0[n] + bias1[n], bias0[n + 1] + bias1[n + 1]);
#pragma unroll
        for (int mi = 0; mi < 4; ++mi) {
            int m0 = mTop + mi * 16;
            if (m0 < nRows) {
                float2 v = make_float2(acc[mi][ni][0] + bv.x, acc[mi][ni][1] + bv.y);
                *(float2*)(xp + (long)m0 * GG + n) = v;
            }
            int m1 = m0 + 8;
            if (m1 < nRows) {
                float2 v = make_float2(acc[mi][ni][2] + bv.x, acc[mi][ni][3] + bv.y);
                *(float2*)(xp + (long)m1 * GG + n) = v;
            }
        }
    }
}

// ---------------------------------------------------------------------------
// Persistent fused LSTM recurrence (R14 core: 2-chunk staging, 128 thr,
// 2 rows/thread) + fp16 decoder-h store (fc A operand, convA fused away).
// ---------------------------------------------------------------------------
__device__ __forceinline__ float sigf(float x) { return 1.f / (1.f + __expf(-x)); }

__device__ __forceinline__ void grid_sync() {
    __syncthreads();
    if (threadIdx.x == 0) {
        unsigned t;
        asm volatile("atom.add.acq_rel.gpu.u32 %0, [%1], 1;"
                     : "=r"(t) : "l"(&g_arrive) : "memory");
        unsigned target = t / (unsigned)RGRID + 1u;
        if ((t % (unsigned)RGRID) == (unsigned)(RGRID - 1)) {
            asm volatile("st.release.gpu.u32 [%0], %1;"
                         :: "l"(&g_epoch), "r"(target) : "memory");
        } else {
            unsigned e;
            do {
                asm volatile("ld.acquire.gpu.u32 %0, [%1];"
                             : "=r"(e) : "l"(&g_epoch) : "memory");
            } while (e < target);
        }
    }
    __syncthreads();
}

__device__ __forceinline__ void cp16(float* smem, const float* gmem) {
    unsigned s = (unsigned)__cvta_generic_to_shared(smem);
    asm volatile("cp.async.ca.shared.global [%0], [%1], 16;" :: "r"(s), "l"(gmem));
}

#define FMA2(acc, a, b) \
    asm("fma.rn.f32x2 %0, %1, %2, %0;" : "+l"(acc) : "l"(a), "l"(b))

__device__ __forceinline__ float2 unpack2(unsigned long long v) {
    float2 f;
    asm("mov.b64 {%0, %1}, %2;" : "=f"(f.x), "=f"(f.y) : "l"(v));
    return f;
}
__device__ __forceinline__ float red4(unsigned long long a, unsigned long long b) {
    float2 p = unpack2(a), q = unpack2(b);
    return (p.x + q.x) + (p.y + q.y);
}

#define WS_STRIDE 516
#define WS_FLOATS (16 * WS_STRIDE)
#define HS_FLOATS (64 * WS_STRIDE)

#define REC_HALF(k0)                                                        \
    _Pragma("unroll 2")                                                     \
    for (int k = (k0); k < (k0) + 256; k += 4) {                            \
        ulonglong2 h1 = *(const ulonglong2*)(hr1 + k);                      \
        ulonglong2 h2 = *(const ulonglong2*)(hr2 + k);                      \
        ulonglong2 w0 = *(const ulonglong2*)(wp0 + k);                      \
        ulonglong2 w1 = *(const ulonglong2*)(wp1 + k);                      \
        ulonglong2 w2 = *(const ulonglong2*)(wp2 + k);                      \
        ulonglong2 w3 = *(const ulonglong2*)(wp3 + k);                      \
        FMA2(B10a, h1.x, w0.x); FMA2(B10b, h1.y, w0.y);                     \
        FMA2(B11a, h1.x, w1.x); FMA2(B11b, h1.y, w1.y);                     \
        FMA2(B12a, h1.x, w2.x); FMA2(B12b, h1.y, w2.y);                     \
        FMA2(B13a, h1.x, w3.x); FMA2(B13b, h1.y, w3.y);                     \
        FMA2(B20a, h2.x, w0.x); FMA2(B20b, h2.y, w0.y);                     \
        FMA2(B21a, h2.x, w1.x); FMA2(B21b, h2.y, w1.y);                     \
        FMA2(B22a, h2.x, w2.x); FMA2(B22b, h2.y, w2.y);                     \
        FMA2(B23a, h2.x, w3.x); FMA2(B23b, h2.y, w3.y);                     \
    }

__global__ __launch_bounds__(128, 1) void lstm_persistent(
    const float* __restrict__ xpE, const float* __restrict__ xpD,
    const float* __restrict__ Wenc, const float* __restrict__ Wdec,
    float* __restrict__ hbuf, __half* __restrict__ ahf)
{
    extern __shared__ float sm[];
    float* w_s = sm;                    // 16 x 516
    float* h_s = sm + WS_FLOATS;        // 64 x 516
    float* c_s = h_s + HS_FLOATS;       // 256

    const int tid = threadIdx.x;        // 0..127
    const int d   = tid & 3;            // hidden unit within CTA
    const int rr  = tid >> 2;           // 0..31; thread owns rows rr, rr+32
    const int J   = blockIdx.x * 4;     // hidden base

    for (int i = tid; i < 16 * 128; i += 128) {
        int c = i >> 7, q = (i & 127) << 2;
        int row = (c >> 2) * 512 + J + (c & 3);
        *(float4*)(w_s + c * WS_STRIDE + q) = *(const float4*)(Wenc + (long)row * HH + q);
    }
    hbuf[(long)rr * HH + J + d] = 0.f;
    hbuf[(long)(rr + 32) * HH + J + d] = 0.f;
    c_s[tid] = 0.f;
    c_s[tid + 128] = 0.f;
    grid_sync();

    const float* hr1 = h_s + rr * WS_STRIDE;
    const float* hr2 = h_s + (rr + 32) * WS_STRIDE;
    const float* wp0 = w_s + (0  + d) * WS_STRIDE;
    const float* wp1 = w_s + (4  + d) * WS_STRIDE;
    const float* wp2 = w_s + (8  + d) * WS_STRIDE;
    const float* wp3 = w_s + (12 + d) * WS_STRIDE;

    const long xb1 = (long)rr * GG + J + d;
    const long xb2 = (long)(rr + 32) * GG + J + d;
    float a10 = xpE[xb1], a11 = xpE[xb1 + 512], a12 = xpE[xb1 + 1024], a13 = xpE[xb1 + 1536];
    float a20 = xpE[xb2], a21 = xpE[xb2 + 512], a22 = xpE[xb2 + 1024], a23 = xpE[xb2 + 1536];

    for (int t = 0; t < NSTEP; ++t) {
        // stage h[t] into SMEM in two 256-col chunks via cp.async
        const float* hin = hbuf + (t & 1) * (BB * HH);
#pragma unroll
        for (int c = 0; c < 2; ++c) {
#pragma unroll
            for (int i = 0; i < 32; ++i) {
                int idx = i * 128 + tid;                 // 0..4095
                int r2 = idx >> 6, q = (idx & 63) << 2;
                cp16(h_s + r2 * WS_STRIDE + c * 256 + q,
                     hin + r2 * HH + c * 256 + q);
            }
            CP_COMMIT();
        }
        if (t == SS) {
            for (int i = tid; i < 16 * 128; i += 128) {
                int c = i >> 7, q = (i & 127) << 2;
                int row = (c >> 2) * 512 + J + (c & 3);
                *(float4*)(w_s + c * WS_STRIDE + q) = *(const float4*)(Wdec + (long)row * HH + q);
            }
        }

        unsigned long long B10a = 0, B10b = 0, B11a = 0, B11b = 0;
        unsigned long long B12a = 0, B12b = 0, B13a = 0, B13b = 0;
        unsigned long long B20a = 0, B20b = 0, B21a = 0, B21b = 0;
        unsigned long long B22a = 0, B22b = 0, B23a = 0, B23b = 0;

        CP_WAIT(1); __syncthreads(); REC_HALF(0);
        CP_WAIT(0); __syncthreads(); REC_HALF(256);

        float gi1 = a10 + red4(B10a, B10b), gf1 = a11 + red4(B11a, B11b);
        float gg1 = a12 + red4(B12a, B12b), go1 = a13 + red4(B13a, B13b);
        float gi2 = a20 + red4(B20a, B20b), gf2 = a21 + red4(B21a, B21b);
        float gg2 = a22 + red4(B22a, B22b), go2 = a23 + red4(B23a, B23b);

        float cn1 = sigf(gf1) * c_s[tid] + sigf(gi1) * tanhf(gg1);
        float hn1 = sigf(go1) * tanhf(cn1);
        c_s[tid] = cn1;
        float cn2 = sigf(gf2) * c_s[tid + 128] + sigf(gi2) * tanhf(gg2);
        float hn2 = sigf(go2) * tanhf(cn2);
        c_s[tid + 128] = cn2;

        float* hout = hbuf + ((t + 1) & 1) * (BB * HH);
        hout[(long)rr * HH + J + d] = hn1;
        hout[(long)(rr + 32) * HH + J + d] = hn2;
        if (t >= SS) {   // fc A operand directly in fp16 (convA fused away)
            __half* hq = ahf + (long)(t - SS) * (BB * HH);
            hq[(long)rr * HH + J + d] = __float2half_rn(hn1);
            hq[(long)(rr + 32) * HH + J + d] = __float2half_rn(hn2);
        }

        if (t + 1 < NSTEP) {
            const float* nxp = (t + 1 < SS) ? (xpE + (long)(t + 1) * (BB * GG))
                                            : (xpD + (long)(t + 1 - SS) * (BB * GG));
            a10 = nxp[xb1]; a11 = nxp[xb1 + 512];
            a12 = nxp[xb1 + 1024]; a13 = nxp[xb1 + 1536];
            a20 = nxp[xb2]; a21 = nxp[xb2 + 512];
            a22 = nxp[xb2 + 1024]; a23 = nxp[xb2 + 1536];
        }

        grid_sync();
    }
}

// ---------------------------------------------------------------------------
// kernel_launch
// ---------------------------------------------------------------------------
extern "C" void kernel_launch(void* const* d_in, const int* in_sizes, int n_in,
                              void* d_out, int out_size) {
    (void)in_sizes; (void)n_in; (void)out_size;
    const int*   src     = (const int*)  d_in[0];
    const int*   tgt     = (const int*)  d_in[1];
    const float* enc_emb = (const float*)d_in[2];
    const float* dec_emb = (const float*)d_in[3];
    const float* enc_Wih = (const float*)d_in[4];
    const float* enc_Whh = (const float*)d_in[5];
    const float* enc_bih = (const float*)d_in[6];
    const float* enc_bhh = (const float*)d_in[7];
    const float* dec_Wih = (const float*)d_in[8];
    const float* dec_Whh = (const float*)d_in[9];
    const float* dec_bih = (const float*)d_in[10];
    const float* dec_bhh = (const float*)d_in[11];
    const float* fc_W    = (const float*)d_in[12];
    const float* fc_b    = (const float*)d_in[13];
    float* out = (float*)d_out;

    float *xpE, *xpD, *hb;
    __half *whf, *ahf, *embE, *embD, *wihE, *wihD;
    cudaGetSymbolAddress((void**)&xpE, g_xp_enc);
    cudaGetSymbolAddress((void**)&xpD, g_xp_dec);
    cudaGetSymbolAddress((void**)&hb,  g_h);
    cudaGetSymbolAddress((void**)&whf, g_Whf);
    cudaGetSymbolAddress((void**)&ahf, g_Ahf);
    cudaGetSymbolAddress((void**)&embE, g_embE);
    cudaGetSymbolAddress((void**)&embD, g_embD);
    cudaGetSymbolAddress((void**)&wihE, g_wihE);
    cudaGetSymbolAddress((void**)&wihD, g_wihD);

    const int recSmem = (WS_FLOATS + HS_FLOATS + 256) * sizeof(float);  // ~166 KB
    cudaFuncSetAttribute(lstm_persistent,
                         cudaFuncAttributeMaxDynamicSharedMemorySize, recSmem);
    const int fcSmem = 2 * FC_STG;                                      // 96 KB
    cudaFuncSetAttribute(fc_f16,
                         cudaFuncAttributeMaxDynamicSharedMemorySize, fcSmem);

    // #1 merged xp-table conversions (embE, embD, wihE, wihD)
    {
        long total = 2L * VV * EE + 2L * GG * EE;
        conv4_f16<<<(int)((total / 8 + 255) / 256), 256>>>(
            enc_emb, dec_emb, enc_Wih, dec_Wih, embE, embD, wihE, wihD);
    }

    // #2, #3 xp GEMMs on fp16 tensor cores
    xp_f16<<<dim3(GG / 128, NENC / 128), 128>>>(
        embE, src, SS, NENC, wihE, enc_bih, enc_bhh, xpE);
    xp_f16<<<dim3(GG / 128, (NDEC + 127) / 128), 128>>>(
        embD, tgt, 32, NDEC, wihD, dec_bih, dec_bhh, xpD);

    // #4 fused persistent recurrence (writes fp16 A for fc directly)
    lstm_persistent<<<RGRID, 128, recSmem>>>(xpE, xpD, enc_Whh, dec_Whh, hb, ahf);

    // #5 zero out[:,0,:]
    init_kernel<<<(BB * VV / 4 + 255) / 256, 256>>>(out);

    // #6 fc_W -> fp16
    {
        long n = (long)VV * HH;
        conv_f16<<<(int)((n / 8 + 255) / 256), 256>>>(fc_W, n, whf, n);
    }

    // #7 vocab projection on fp16 tensor cores -> out[b][t+1][v]
    fc_f16<<<dim3(VV / FC_BN, MPAD / 128), 512, fcSmem>>>(ahf, whf, fc_b, out);
}